// round 13
// baseline (speedup 1.0000x reference)
#include <cuda_runtime.h>
#include <math.h>

#define N_NODES 4096
#define N_EDGES 8192
#define DIMQ    4096

// ---------------- device scratch (no allocations allowed) ----------------
__device__ float g_boT[4 * N_EDGES];   // bo transposed [f][j], ref f32 semantics
__device__ float g_biT[4 * N_EDGES];
__device__ float g_mi[N_NODES * 4];
__device__ float g_mo[N_NODES * 4];
__device__ float g_cs[33];
__device__ float g_sn[33];

// ---------------- init: precompute theta trig ----------------
__global__ void init_kernel(const float* __restrict__ theta) {
    int i = threadIdx.x;
    if (i < 33) {
        double h = 0.5 * (double)theta[i];
        g_cs[i] = (float)cos(h);
        g_sn[i] = (float)sin(h);
    }
}

// ---------------- phase 1: bo = Ro^T X, bi = Ri^T X ----------------
// Ref semantics (confirmed r6): per (j,f), 4 lanes over n==l (mod 4) ascending,
// acc_l = fma(A[n,j], X[n,f], acc_l); combine ((l0+l1)+(l2+l3)).
// DIRECT-LDG: warp = 32 consecutive j at one row -> each LDG.32 is a perfect
// 128B coalesced line. X via __ldg (L1-resident, warp-broadcast). No smem tiles.
__global__ void __launch_bounds__(128) phase1_kernel(const float* __restrict__ Ri,
                                                     const float* __restrict__ Ro,
                                                     const float* __restrict__ X) {
    int mat = blockIdx.x & 1;
    const float* A = mat ? Ri : Ro;
    float* dst     = mat ? g_biT : g_boT;
    int j0  = (int)(blockIdx.x >> 1) * 32;
    int tid = threadIdx.x;
    int jl = tid & 31, l = tid >> 5;             // warp owns lane l

    __shared__ float pacc[4][4][32];             // [l][f][jl]

    const float*  colp = A + j0 + jl;
    const float4* X4   = (const float4*)X;

    float a0 = 0.f, a1 = 0.f, a2 = 0.f, a3 = 0.f;
    for (int t = 0; t < N_NODES / 4; t += 8) {   // n = 4(t+u)+l ascending
        #pragma unroll
        for (int u = 0; u < 8; u++) {
            int n = (t + u) * 4 + l;
            float  a = __ldg(colp + (size_t)n * N_EDGES);
            float4 x = __ldg(&X4[n]);
            a0 = __fmaf_rn(a, x.x, a0);
            a1 = __fmaf_rn(a, x.y, a1);
            a2 = __fmaf_rn(a, x.z, a2);
            a3 = __fmaf_rn(a, x.w, a3);
        }
    }
    pacc[l][0][jl] = a0; pacc[l][1][jl] = a1;
    pacc[l][2][jl] = a2; pacc[l][3][jl] = a3;
    __syncthreads();
    // combine ((l0+l1)+(l2+l3)), one thread per (f, jl)
    {
        int f = l;                               // reuse tid = f*32 + jl layout
        float x = __fadd_rn(__fadd_rn(pacc[0][f][jl], pacc[1][f][jl]),
                            __fadd_rn(pacc[2][f][jl], pacc[3][f][jl]));
        dst[(size_t)f * N_EDGES + j0 + jl] = x;
    }
}

// ---------------- phase 2: mi = (Ri.*e) @ bo, mo = (Ro.*e) @ bi ----------------
// Ref semantics (confirmed): 4-lane mod-4 ascending FMA chains over j,
// term = fl32(A[n,j]*e[j]), combined ((l0+l1)+(l2+l3)).
// DIRECT-LDG for the streaming matrix (rows contiguous, unroll-8 walks 128B
// lines); e + boT/biT staged ONCE per 2048-j chunk in smem (no pipeline).
#define P2_NB 32
#define P2_CH 2048
__global__ void __launch_bounds__(128) phase2_kernel(const float* __restrict__ Ri,
                                                     const float* __restrict__ Ro,
                                                     const float* __restrict__ e) {
    int mat = blockIdx.x & 1;            // 0: mi (Ri, boT), 1: mo (Ro, biT)
    const float* A  = mat ? Ro : Ri;
    const float* BT = mat ? g_biT : g_boT;
    float* dst      = mat ? g_mo : g_mi;
    int n0  = (int)(blockIdx.x >> 1) * P2_NB;
    int tid = threadIdx.x;
    int f = tid & 3, nl = tid >> 2;
    int n = n0 + nl;

    __shared__ __align__(16) float es[P2_CH];        // 8KB
    __shared__ __align__(16) float bts[4][P2_CH];    // 32KB

    const float4* row4 = (const float4*)(A + (size_t)n * N_EDGES);

    float a0 = 0.f, a1 = 0.f, a2 = 0.f, a3 = 0.f;
    for (int c = 0; c < N_EDGES / P2_CH; c++) {      // 4 chunks, j ascending
        int jb = c * P2_CH;
        __syncthreads();
        for (int i = tid; i < P2_CH / 4; i += 128)
            ((float4*)es)[i] = __ldg((const float4*)(e + jb) + i);
        #pragma unroll
        for (int ff = 0; ff < 4; ff++)
            for (int i = tid; i < P2_CH / 4; i += 128)
                ((float4*)bts[ff])[i] =
                    __ldg((const float4*)(BT + (size_t)ff * N_EDGES + jb) + i);
        __syncthreads();

        int qb = jb / 4;
        #pragma unroll 8
        for (int q = 0; q < P2_CH / 4; q++) {        // j = jb+4q+lane ascending
            float4 av = __ldg(&row4[qb + q]);
            float4 ev = *(const float4*)&es[q * 4];
            float4 bv = *(const float4*)&bts[f][q * 4];
            a0 = __fmaf_rn(__fmul_rn(av.x, ev.x), bv.x, a0);
            a1 = __fmaf_rn(__fmul_rn(av.y, ev.y), bv.y, a1);
            a2 = __fmaf_rn(__fmul_rn(av.z, ev.z), bv.z, a2);
            a3 = __fmaf_rn(__fmul_rn(av.w, ev.w), bv.w, a3);
        }
    }
    // adjacent pairwise combine: ((l0+l1)+(l2+l3))
    float x = __fadd_rn(__fadd_rn(a0, a1), __fadd_rn(a2, a3));
    dst[n * 4 + f] = x;
}

// ---------------- circuit: 8 register-resident passes (r8 version, proven) ----------------
#define SWZ(x) ((x) ^ (((x) >> 4) & 31))
#define PAT4(p, S0,S1,S2,S3) (((((p)>>0)&1)<<(S0)) | ((((p)>>1)&1)<<(S1)) | \
                              ((((p)>>2)&1)<<(S2)) | ((((p)>>3)&1)<<(S3)))
#define LD16(S0,S1,S2,S3) { _Pragma("unroll") \
    for (int p_ = 0; p_ < 16; p_++) v[p_] = st[sb ^ SWZ(PAT4(p_,S0,S1,S2,S3))]; }
#define ST16(S0,S1,S2,S3) { _Pragma("unroll") \
    for (int p_ = 0; p_ < 16; p_++) st[sb ^ SWZ(PAT4(p_,S0,S1,S2,S3))] = v[p_]; }
#define RY16(K, TI) { const float c_ = cst[TI], s_ = snt[TI]; \
    _Pragma("unroll") for (int i_ = 0; i_ < 16; i_++) if (!((i_ >> (K)) & 1)) { \
        int i1_ = i_ | (1 << (K)); \
        float a0_ = v[i_], a1_ = v[i1_]; \
        v[i_]  = c_ * a0_ - s_ * a1_; \
        v[i1_] = s_ * a0_ + c_ * a1_; } }
#define CX16(KC, KT) { _Pragma("unroll") \
    for (int i_ = 0; i_ < 16; i_++) if (((i_ >> (KC)) & 1) && !((i_ >> (KT)) & 1)) { \
        int i1_ = i_ | (1 << (KT)); \
        float tp_ = v[i_]; v[i_] = v[i1_]; v[i1_] = tp_; } }

__global__ void __launch_bounds__(256) circuit_kernel(const float* __restrict__ X,
                                                      float* __restrict__ out) {
    __shared__ float  st[DIMQ];
    __shared__ float  cw[12], sw[12];
    __shared__ float  cst[33], snt[33];
    __shared__ double redsm[8];

    int b = blockIdx.x, tid = threadIdx.x;

    if (tid < 12) {
        float angf = (tid < 4) ? g_mi[b * 4 + tid]
                   : (tid < 8) ? g_mo[b * 4 + tid - 4]
                               : X[b * 4 + tid - 8];
        double h = 0.5 * (double)angf;   // f64 trig: exact range reduction
        cw[tid] = (float)cos(h);
        sw[tid] = (float)sin(h);
    }
    if (tid < 33) { cst[tid] = g_cs[tid]; snt[tid] = g_sn[tid]; }
    __syncthreads();

    float v[16];

    // ---- PASS 1: S={7,8,9,10} (wires 4,3,2,1); init product fused in
    {
        int base = (tid & 127) | (((tid >> 7) & 1) << 11);
        float pb;
        pb  = ((base >> 11) & 1) ? sw[0]  : cw[0];
        pb *= ((base >> 6)  & 1) ? sw[5]  : cw[5];
        pb *= ((base >> 5)  & 1) ? sw[6]  : cw[6];
        pb *= ((base >> 4)  & 1) ? sw[7]  : cw[7];
        pb *= ((base >> 3)  & 1) ? sw[8]  : cw[8];
        pb *= ((base >> 2)  & 1) ? sw[9]  : cw[9];
        pb *= ((base >> 1)  & 1) ? sw[10] : cw[10];
        pb *= ((base >> 0)  & 1) ? sw[11] : cw[11];
        float f40 = cw[4], f41 = sw[4], f30 = cw[3], f31 = sw[3];
        float f20 = cw[2], f21 = sw[2], f10 = cw[1], f11 = sw[1];
        #pragma unroll
        for (int p = 0; p < 16; p++)
            v[p] = pb * ((p & 1) ? f41 : f40) * ((p & 2) ? f31 : f30)
                      * ((p & 4) ? f21 : f20) * ((p & 8) ? f11 : f10);
        RY16(3, 0)  RY16(2, 1)  CX16(3, 2)      // T0: cx1->2
        RY16(1, 2)  RY16(0, 3)  CX16(0, 1)      // T1: cx4->3
        int sb = SWZ(base);
        ST16(7, 8, 9, 10)
    }
    __syncthreads();

    // ---- PASS 2: S={3,4,5,6} (wires 8,7,6,5)
    {
        int base = (tid & 7) | (((tid >> 3) & 31) << 7);
        int sb = SWZ(base);
        LD16(3, 4, 5, 6)
        RY16(3, 4)  RY16(2, 5)  CX16(3, 2)      // T2: cx5->6
        RY16(1, 6)  RY16(0, 7)  CX16(1, 0)      // T3: cx7->8
        ST16(3, 4, 5, 6)
    }
    __syncthreads();

    // ---- PASS 3: S={1,2,10,11} (wires 10,9,1,0)
    {
        int base = (tid & 1) | (((tid >> 1) & 15) << 3) | (((tid >> 5) & 7) << 7);
        int sb = SWZ(base);
        LD16(1, 2, 10, 11)
        RY16(1, 8)  RY16(0, 9)  CX16(0, 1)      // T4: cx10->9
        RY16(3, 10) RY16(2, 11) CX16(3, 2)      // T5: cx0->1
        ST16(1, 2, 10, 11)
    }
    __syncthreads();

    // ---- PASS 4: S={6,7,8,9} (wires 5,4,3,2)
    {
        int base = (tid & 31) | (((tid >> 5) & 1) << 5) | (((tid >> 6) & 3) << 10);
        int sb = SWZ(base);
        LD16(6, 7, 8, 9)
        RY16(3, 12) RY16(2, 13) CX16(2, 3)      // T6: cx3->2
        RY16(1, 14) RY16(0, 15) CX16(1, 0)      // T7: cx4->5
        ST16(6, 7, 8, 9)
    }
    __syncthreads();

    // ---- PASS 5: S={2,3,4,5} (wires 9,8,7,6)
    {
        int base = (tid & 3) | (((tid >> 2) & 7) << 6) | (((tid >> 5) & 7) << 9);
        int sb = SWZ(base);
        LD16(2, 3, 4, 5)
        RY16(3, 16) RY16(2, 17) CX16(2, 3)      // T8: cx7->6
        RY16(1, 18) RY16(0, 19) CX16(1, 0)      // T9: cx8->9
        ST16(2, 3, 4, 5)
    }
    __syncthreads();

    // ---- PASS 6: S={0,1,6,9} (wires 11,10,5,2)
    {
        int base = ((tid & 15) << 2) | (((tid >> 4) & 1) << 8)
                 | (((tid >> 5) & 1) << 7) | (((tid >> 6) & 3) << 10);
        int sb = SWZ(base);
        LD16(0, 1, 6, 9)
        RY16(1, 20) RY16(0, 21) CX16(0, 1)      // T10: cx11->10
        RY16(3, 22) RY16(2, 23) CX16(2, 3)      // T11: cx5->2
        ST16(0, 1, 6, 9)
    }
    __syncthreads();

    // ---- PASS 7: S={2,5,9,10} (wires 9,6,2,1)
    {
        int base = (tid & 3) | (((tid >> 2) & 3) << 3) | (((tid >> 4) & 1) << 6)
                 | (((tid >> 5) & 3) << 7) | (((tid >> 7) & 1) << 11);
        int sb = SWZ(base);
        LD16(2, 5, 9, 10)
        RY16(1, 24) RY16(0, 25) CX16(1, 0)      // T12: cx6->9
        RY16(3, 26) RY16(2, 27) CX16(3, 2)      // T13: cx1->2
        ST16(2, 5, 9, 10)
    }
    __syncthreads();

    // ---- PASS 8: S={0,1,2,9} (wires 11,10,9,2); expz fused (slot 2 = wire 9)
    float local = 0.0f;
    {
        int base = ((tid & 15) << 3) | (((tid >> 4) & 1) << 8)
                 | (((tid >> 5) & 1) << 7) | (((tid >> 6) & 3) << 10);
        int sb = SWZ(base);
        LD16(0, 1, 2, 9)
        RY16(2, 28) RY16(1, 29) CX16(1, 2)      // T14: cx10->9
        RY16(3, 30) RY16(2, 31) CX16(3, 2)      // T15: cx2->9
        RY16(2, 32)                              // final ry@9
        #pragma unroll
        for (int p = 0; p < 16; p++) {
            float v2 = v[p] * v[p];
            local += (p & 4) ? -v2 : v2;
        }
    }

    double dv = (double)local;
    #pragma unroll
    for (int o = 16; o > 0; o >>= 1) dv += __shfl_down_sync(0xffffffffu, dv, o);
    int lane = tid & 31, wp = tid >> 5;
    if (lane == 0) redsm[wp] = dv;
    __syncthreads();
    if (tid == 0) {
        double expz = 0.0;
        for (int w = 0; w < 8; w++) expz += redsm[w];
        out[b] = (float)(1.5707963267948966 * (1.0 - expz));
    }
}

// ---------------- launch ----------------
extern "C" void kernel_launch(void* const* d_in, const int* in_sizes, int n_in,
                              void* d_out, int out_size) {
    const float *X = 0, *e = 0, *Ri = 0, *Ro = 0, *th = 0;
    for (int i = 0; i < n_in; i++) {
        int s = in_sizes[i];
        const float* p = (const float*)d_in[i];
        if (s == N_NODES * 4)            X = p;
        else if (s == N_EDGES)           e = p;
        else if (s == 33)                th = p;
        else if (s == N_NODES * N_EDGES) { if (!Ri) Ri = p; else Ro = p; }
    }
    float* out = (float*)d_out;

    init_kernel<<<1, 64>>>(th);
    phase1_kernel<<<(N_EDGES / 32) * 2, 128>>>(Ri, Ro, X);
    phase2_kernel<<<(N_NODES / P2_NB) * 2, 128>>>(Ri, Ro, e);
    circuit_kernel<<<N_NODES, 256>>>(X, out);
}

// round 14
// speedup vs baseline: 2.3142x; 2.3142x over previous
#include <cuda_runtime.h>
#include <math.h>

#define N_NODES 4096
#define N_EDGES 8192
#define DIMQ    4096

// ---------------- device scratch (no allocations allowed) ----------------
// g_eb[mat][j][f] = (e[j], bT[f][j])  -- packed for phase2's single LDS64
__device__ __align__(16) float2 g_eb[2][N_EDGES][4];
__device__ float g_mi[N_NODES * 4];
__device__ float g_mo[N_NODES * 4];
__device__ float g_cs[33];
__device__ float g_sn[33];

// ---------------- cp.async helpers ----------------
__device__ __forceinline__ unsigned smem_u32(const void* p) {
    return (unsigned)__cvta_generic_to_shared(p);
}
__device__ __forceinline__ void cp_async16(void* dst, const void* src) {
    asm volatile("cp.async.cg.shared.global [%0], [%1], 16;"
                 :: "r"(smem_u32(dst)), "l"(src));
}
__device__ __forceinline__ void cp_commit() {
    asm volatile("cp.async.commit_group;");
}
template<int N> __device__ __forceinline__ void cp_wait() {
    asm volatile("cp.async.wait_group %0;" :: "n"(N));
}

// ---------------- phase 1: bo = Ro^T X, bi = Ri^T X (R8-proven structure) ----------------
// Ref semantics (confirmed r6): per (j,f), 4 lanes over n==l (mod 4) ascending,
// acc_l = fma(A[n,j], X[n,f], acc_l); combine ((l0+l1)+(l2+l3)).
// Emits packed (e[j], bT[f][j]) into g_eb. Theta trig folded into block 0.
#define P1_BJ 32
#define P1_BN 128
#define P1_LD 36
__global__ void __launch_bounds__(128) phase1_kernel(const float* __restrict__ Ri,
                                                     const float* __restrict__ Ro,
                                                     const float* __restrict__ X,
                                                     const float* __restrict__ e,
                                                     const float* __restrict__ theta) {
    int mat = blockIdx.x & 1;                    // 0: Ro -> ebo, 1: Ri -> ebi
    const float* A = mat ? Ri : Ro;
    int j0  = (int)(blockIdx.x >> 1) * P1_BJ;
    int tid = threadIdx.x;
    int jl = tid & 31, l = tid >> 5;             // warp = lane index l

    if (blockIdx.x == 0 && tid < 33) {           // init fold (runs before circuit)
        double h = 0.5 * (double)theta[tid];
        g_cs[tid] = (float)cos(h);
        g_sn[tid] = (float)sin(h);
    }

    __shared__ __align__(16) float  tile[2][P1_BN][P1_LD];
    __shared__ float4 xs[2][P1_BN];
    __shared__ float  pacc[4][4][32];            // [l][f][jl]

    auto stage = [&](int t, int s) {
        int n0 = t * P1_BN;
        const float* base = A + (size_t)n0 * N_EDGES + j0;
        #pragma unroll
        for (int o = 0; o < 8; o++) {
            int idx = o * 128 + tid;             // 1024 float4
            int row = idx >> 3, c4 = idx & 7;
            cp_async16(&tile[s][row][c4 * 4], base + (size_t)row * N_EDGES + c4 * 4);
        }
        cp_async16(&xs[s][tid], X + (size_t)(n0 + tid) * 4);
        cp_commit();
    };

    stage(0, 0);
    float a0 = 0.f, a1 = 0.f, a2 = 0.f, a3 = 0.f;
    const int NT = N_NODES / P1_BN;              // 32
    for (int t = 0; t < NT; t++) {
        int s = t & 1;
        if (t + 1 < NT) { stage(t + 1, s ^ 1); cp_wait<1>(); }
        else            { cp_wait<0>(); }
        __syncthreads();
        #pragma unroll 8
        for (int i = 0; i < P1_BN / 4; i++) {
            int row = i * 4 + l;
            float  a = tile[s][row][jl];
            float4 x = xs[s][row];
            a0 = __fmaf_rn(a, x.x, a0);
            a1 = __fmaf_rn(a, x.y, a1);
            a2 = __fmaf_rn(a, x.z, a2);
            a3 = __fmaf_rn(a, x.w, a3);
        }
        __syncthreads();
    }
    pacc[l][0][jl] = a0; pacc[l][1][jl] = a1;
    pacc[l][2][jl] = a2; pacc[l][3][jl] = a3;
    __syncthreads();
    // finalize: thread (f=l, jl): combine ((l0+l1)+(l2+l3)); pack with e[j]
    {
        int f = l;
        int j = j0 + jl;
        float x = __fadd_rn(__fadd_rn(pacc[0][f][jl], pacc[1][f][jl]),
                            __fadd_rn(pacc[2][f][jl], pacc[3][f][jl]));
        g_eb[mat][j][f] = make_float2(e[j], x);
    }
}

// ---------------- phase 2: mi = (Ri.*e) @ bo, mo = (Ro.*e) @ bi ----------------
// Ref semantics (confirmed): 4-lane mod-4 ascending FMA chains over j,
// term = fl32(A[n,j]*e[j]), combined ((l0+l1)+(l2+l3)).
// LANE-SPLIT map: thread = (nl, f, l) -> 131K threads (27.7 warps/SM).
// Per step: 1 LDS32 (A tile) + 1 LDS64 (packed e,bo) + FMUL + FMA.
// Bank layouts verified conflict-free (ebts[j][f]: warp hits all 32 banks once).
#define P2_NB 16
#define P2_JT 128
__global__ void __launch_bounds__(256) phase2_kernel(const float* __restrict__ Ri,
                                                     const float* __restrict__ Ro) {
    int matp = blockIdx.x & 1;           // 0: mi (Ri, ebo), 1: mo (Ro, ebi)
    const float* A = matp ? Ro : Ri;
    float* dst     = matp ? g_mo : g_mi;
    int n0  = (int)(blockIdx.x >> 1) * P2_NB;
    int tid = threadIdx.x;
    int l = tid & 3, f = (tid >> 2) & 3, nl = tid >> 4;    // nl 0..15

    __shared__ __align__(16) float  tileA[2][P2_NB][P2_JT + 4];
    __shared__ __align__(16) float2 ebts[2][P2_JT][4];

    auto stage = [&](int t, int s) {
        int jt = t * P2_JT;
        const float* base = A + (size_t)n0 * N_EDGES + jt;
        #pragma unroll
        for (int o = 0; o < 2; o++) {
            int idx = o * 256 + tid;             // 512 float4
            int row = idx >> 5, c4 = idx & 31;
            cp_async16(&tileA[s][row][c4 * 4], base + (size_t)row * N_EDGES + c4 * 4);
        }
        {
            int j = tid >> 1, half = tid & 1;    // 256 x 16B covers 128 j x 4 f
            cp_async16(&ebts[s][j][half * 2], &g_eb[matp][jt + j][half * 2]);
        }
        cp_commit();
    };

    const int NT = N_EDGES / P2_JT;              // 64
    stage(0, 0);
    float acc = 0.f;
    for (int t = 0; t < NT; t++) {
        int s = t & 1;
        if (t + 1 < NT) { stage(t + 1, s ^ 1); cp_wait<1>(); }
        else            { cp_wait<0>(); }
        __syncthreads();
        #pragma unroll
        for (int i = 0; i < P2_JT / 4; i++) {
            int jj = i * 4 + l;                  // j = jt + 4i + l ascending
            float  a  = tileA[s][nl][jj];
            float2 eb = ebts[s][jj][f];
            acc = __fmaf_rn(__fmul_rn(a, eb.x), eb.y, acc);
        }
        __syncthreads();
    }
    // ((l0+l1)+(l2+l3)) via warp shuffles (lanes are tid bits 0-1)
    unsigned m = 0xffffffffu;
    float x1 = __fadd_rn(acc, __shfl_xor_sync(m, acc, 1));
    float x2 = __fadd_rn(x1,  __shfl_xor_sync(m, x1, 2));
    if (l == 0) dst[(n0 + nl) * 4 + f] = x2;
}

// ---------------- circuit: 8 register-resident passes (r8 version, proven) ----------------
#define SWZ(x) ((x) ^ (((x) >> 4) & 31))
#define PAT4(p, S0,S1,S2,S3) (((((p)>>0)&1)<<(S0)) | ((((p)>>1)&1)<<(S1)) | \
                              ((((p)>>2)&1)<<(S2)) | ((((p)>>3)&1)<<(S3)))
#define LD16(S0,S1,S2,S3) { _Pragma("unroll") \
    for (int p_ = 0; p_ < 16; p_++) v[p_] = st[sb ^ SWZ(PAT4(p_,S0,S1,S2,S3))]; }
#define ST16(S0,S1,S2,S3) { _Pragma("unroll") \
    for (int p_ = 0; p_ < 16; p_++) st[sb ^ SWZ(PAT4(p_,S0,S1,S2,S3))] = v[p_]; }
#define RY16(K, TI) { const float c_ = cst[TI], s_ = snt[TI]; \
    _Pragma("unroll") for (int i_ = 0; i_ < 16; i_++) if (!((i_ >> (K)) & 1)) { \
        int i1_ = i_ | (1 << (K)); \
        float a0_ = v[i_], a1_ = v[i1_]; \
        v[i_]  = c_ * a0_ - s_ * a1_; \
        v[i1_] = s_ * a0_ + c_ * a1_; } }
#define CX16(KC, KT) { _Pragma("unroll") \
    for (int i_ = 0; i_ < 16; i_++) if (((i_ >> (KC)) & 1) && !((i_ >> (KT)) & 1)) { \
        int i1_ = i_ | (1 << (KT)); \
        float tp_ = v[i_]; v[i_] = v[i1_]; v[i1_] = tp_; } }

__global__ void __launch_bounds__(256) circuit_kernel(const float* __restrict__ X,
                                                      float* __restrict__ out) {
    __shared__ float  st[DIMQ];
    __shared__ float  cw[12], sw[12];
    __shared__ float  cst[33], snt[33];
    __shared__ double redsm[8];

    int b = blockIdx.x, tid = threadIdx.x;

    if (tid < 12) {
        float angf = (tid < 4) ? g_mi[b * 4 + tid]
                   : (tid < 8) ? g_mo[b * 4 + tid - 4]
                               : X[b * 4 + tid - 8];
        double h = 0.5 * (double)angf;   // f64 trig: exact range reduction
        cw[tid] = (float)cos(h);
        sw[tid] = (float)sin(h);
    }
    if (tid < 33) { cst[tid] = g_cs[tid]; snt[tid] = g_sn[tid]; }
    __syncthreads();

    float v[16];

    // ---- PASS 1: S={7,8,9,10} (wires 4,3,2,1); init product fused in
    {
        int base = (tid & 127) | (((tid >> 7) & 1) << 11);
        float pb;
        pb  = ((base >> 11) & 1) ? sw[0]  : cw[0];
        pb *= ((base >> 6)  & 1) ? sw[5]  : cw[5];
        pb *= ((base >> 5)  & 1) ? sw[6]  : cw[6];
        pb *= ((base >> 4)  & 1) ? sw[7]  : cw[7];
        pb *= ((base >> 3)  & 1) ? sw[8]  : cw[8];
        pb *= ((base >> 2)  & 1) ? sw[9]  : cw[9];
        pb *= ((base >> 1)  & 1) ? sw[10] : cw[10];
        pb *= ((base >> 0)  & 1) ? sw[11] : cw[11];
        float f40 = cw[4], f41 = sw[4], f30 = cw[3], f31 = sw[3];
        float f20 = cw[2], f21 = sw[2], f10 = cw[1], f11 = sw[1];
        #pragma unroll
        for (int p = 0; p < 16; p++)
            v[p] = pb * ((p & 1) ? f41 : f40) * ((p & 2) ? f31 : f30)
                      * ((p & 4) ? f21 : f20) * ((p & 8) ? f11 : f10);
        RY16(3, 0)  RY16(2, 1)  CX16(3, 2)      // T0: cx1->2
        RY16(1, 2)  RY16(0, 3)  CX16(0, 1)      // T1: cx4->3
        int sb = SWZ(base);
        ST16(7, 8, 9, 10)
    }
    __syncthreads();

    // ---- PASS 2: S={3,4,5,6} (wires 8,7,6,5)
    {
        int base = (tid & 7) | (((tid >> 3) & 31) << 7);
        int sb = SWZ(base);
        LD16(3, 4, 5, 6)
        RY16(3, 4)  RY16(2, 5)  CX16(3, 2)      // T2: cx5->6
        RY16(1, 6)  RY16(0, 7)  CX16(1, 0)      // T3: cx7->8
        ST16(3, 4, 5, 6)
    }
    __syncthreads();

    // ---- PASS 3: S={1,2,10,11} (wires 10,9,1,0)
    {
        int base = (tid & 1) | (((tid >> 1) & 15) << 3) | (((tid >> 5) & 7) << 7);
        int sb = SWZ(base);
        LD16(1, 2, 10, 11)
        RY16(1, 8)  RY16(0, 9)  CX16(0, 1)      // T4: cx10->9
        RY16(3, 10) RY16(2, 11) CX16(3, 2)      // T5: cx0->1
        ST16(1, 2, 10, 11)
    }
    __syncthreads();

    // ---- PASS 4: S={6,7,8,9} (wires 5,4,3,2)
    {
        int base = (tid & 31) | (((tid >> 5) & 1) << 5) | (((tid >> 6) & 3) << 10);
        int sb = SWZ(base);
        LD16(6, 7, 8, 9)
        RY16(3, 12) RY16(2, 13) CX16(2, 3)      // T6: cx3->2
        RY16(1, 14) RY16(0, 15) CX16(1, 0)      // T7: cx4->5
        ST16(6, 7, 8, 9)
    }
    __syncthreads();

    // ---- PASS 5: S={2,3,4,5} (wires 9,8,7,6)
    {
        int base = (tid & 3) | (((tid >> 2) & 7) << 6) | (((tid >> 5) & 7) << 9);
        int sb = SWZ(base);
        LD16(2, 3, 4, 5)
        RY16(3, 16) RY16(2, 17) CX16(2, 3)      // T8: cx7->6
        RY16(1, 18) RY16(0, 19) CX16(1, 0)      // T9: cx8->9
        ST16(2, 3, 4, 5)
    }
    __syncthreads();

    // ---- PASS 6: S={0,1,6,9} (wires 11,10,5,2)
    {
        int base = ((tid & 15) << 2) | (((tid >> 4) & 1) << 8)
                 | (((tid >> 5) & 1) << 7) | (((tid >> 6) & 3) << 10);
        int sb = SWZ(base);
        LD16(0, 1, 6, 9)
        RY16(1, 20) RY16(0, 21) CX16(0, 1)      // T10: cx11->10
        RY16(3, 22) RY16(2, 23) CX16(2, 3)      // T11: cx5->2
        ST16(0, 1, 6, 9)
    }
    __syncthreads();

    // ---- PASS 7: S={2,5,9,10} (wires 9,6,2,1)
    {
        int base = (tid & 3) | (((tid >> 2) & 3) << 3) | (((tid >> 4) & 1) << 6)
                 | (((tid >> 5) & 3) << 7) | (((tid >> 7) & 1) << 11);
        int sb = SWZ(base);
        LD16(2, 5, 9, 10)
        RY16(1, 24) RY16(0, 25) CX16(1, 0)      // T12: cx6->9
        RY16(3, 26) RY16(2, 27) CX16(3, 2)      // T13: cx1->2
        ST16(2, 5, 9, 10)
    }
    __syncthreads();

    // ---- PASS 8: S={0,1,2,9} (wires 11,10,9,2); expz fused (slot 2 = wire 9)
    float local = 0.0f;
    {
        int base = ((tid & 15) << 3) | (((tid >> 4) & 1) << 8)
                 | (((tid >> 5) & 1) << 7) | (((tid >> 6) & 3) << 10);
        int sb = SWZ(base);
        LD16(0, 1, 2, 9)
        RY16(2, 28) RY16(1, 29) CX16(1, 2)      // T14: cx10->9
        RY16(3, 30) RY16(2, 31) CX16(3, 2)      // T15: cx2->9
        RY16(2, 32)                              // final ry@9
        #pragma unroll
        for (int p = 0; p < 16; p++) {
            float v2 = v[p] * v[p];
            local += (p & 4) ? -v2 : v2;
        }
    }

    double dv = (double)local;
    #pragma unroll
    for (int o = 16; o > 0; o >>= 1) dv += __shfl_down_sync(0xffffffffu, dv, o);
    int lane = tid & 31, wp = tid >> 5;
    if (lane == 0) redsm[wp] = dv;
    __syncthreads();
    if (tid == 0) {
        double expz = 0.0;
        for (int w = 0; w < 8; w++) expz += redsm[w];
        out[b] = (float)(1.5707963267948966 * (1.0 - expz));
    }
}

// ---------------- launch ----------------
extern "C" void kernel_launch(void* const* d_in, const int* in_sizes, int n_in,
                              void* d_out, int out_size) {
    const float *X = 0, *e = 0, *Ri = 0, *Ro = 0, *th = 0;
    for (int i = 0; i < n_in; i++) {
        int s = in_sizes[i];
        const float* p = (const float*)d_in[i];
        if (s == N_NODES * 4)            X = p;
        else if (s == N_EDGES)           e = p;
        else if (s == 33)                th = p;
        else if (s == N_NODES * N_EDGES) { if (!Ri) Ri = p; else Ro = p; }
    }
    float* out = (float*)d_out;

    phase1_kernel<<<(N_EDGES / P1_BJ) * 2, 128>>>(Ri, Ro, X, e, th);
    phase2_kernel<<<(N_NODES / P2_NB) * 2, 256>>>(Ri, Ro);
    circuit_kernel<<<N_NODES, 256>>>(X, out);
}

// round 15
// speedup vs baseline: 2.7664x; 1.1954x over previous
#include <cuda_runtime.h>
#include <math.h>

#define N_NODES 4096
#define N_EDGES 8192
#define DIMQ    4096

// ---------------- device scratch (no allocations allowed) ----------------
__device__ float g_boT[4 * N_EDGES];   // bo transposed [f][j], ref f32 semantics
__device__ float g_biT[4 * N_EDGES];
__device__ float g_mi[N_NODES * 4];
__device__ float g_mo[N_NODES * 4];
__device__ float g_cs[33];
__device__ float g_sn[33];

// ---------------- cp.async helpers ----------------
__device__ __forceinline__ unsigned smem_u32(const void* p) {
    return (unsigned)__cvta_generic_to_shared(p);
}
__device__ __forceinline__ void cp_async16(void* dst, const void* src) {
    asm volatile("cp.async.cg.shared.global [%0], [%1], 16;"
                 :: "r"(smem_u32(dst)), "l"(src));
}
__device__ __forceinline__ void cp_commit() {
    asm volatile("cp.async.commit_group;");
}
template<int N> __device__ __forceinline__ void cp_wait() {
    asm volatile("cp.async.wait_group %0;" :: "n"(N));
}

// ---------------- phase 1: bo = Ro^T X, bi = Ri^T X (R8-proven) ----------------
// Ref semantics (confirmed r6): per (j,f), 4 lanes over n==l (mod 4) ascending,
// acc_l = fma(A[n,j], X[n,f], acc_l); combine ((l0+l1)+(l2+l3)).
// MAT-SERIALIZED: blocks [0,256) process Ro (early waves), [256,512) Ri (late),
// so Ri is L2-resident when phase2's mi pass starts. Theta trig folded in.
#define P1_BJ 32
#define P1_BN 128
#define P1_LD 36
__global__ void __launch_bounds__(128) phase1_kernel(const float* __restrict__ Ri,
                                                     const float* __restrict__ Ro,
                                                     const float* __restrict__ X,
                                                     const float* __restrict__ theta) {
    int mat = blockIdx.x >> 8;                   // 0: Ro (first), 1: Ri (last)
    const float* A = mat ? Ri : Ro;
    float* dst     = mat ? g_biT : g_boT;
    int j0  = (int)(blockIdx.x & 255) * P1_BJ;
    int tid = threadIdx.x;
    int jl = tid & 31, l = tid >> 5;             // warp = lane index l

    if (blockIdx.x == 0 && tid < 33) {           // init fold (finishes in phase1)
        double h = 0.5 * (double)theta[tid];
        g_cs[tid] = (float)cos(h);
        g_sn[tid] = (float)sin(h);
    }

    __shared__ __align__(16) float  tile[2][P1_BN][P1_LD];
    __shared__ float4 xs[2][P1_BN];
    __shared__ float  pacc[4][4][32];            // [l][f][jl]

    auto stage = [&](int t, int s) {
        int n0 = t * P1_BN;
        const float* base = A + (size_t)n0 * N_EDGES + j0;
        #pragma unroll
        for (int o = 0; o < 8; o++) {
            int idx = o * 128 + tid;             // 1024 float4
            int row = idx >> 3, c4 = idx & 7;
            cp_async16(&tile[s][row][c4 * 4], base + (size_t)row * N_EDGES + c4 * 4);
        }
        cp_async16(&xs[s][tid], X + (size_t)(n0 + tid) * 4);
        cp_commit();
    };

    stage(0, 0);
    float a0 = 0.f, a1 = 0.f, a2 = 0.f, a3 = 0.f;
    const int NT = N_NODES / P1_BN;              // 32
    for (int t = 0; t < NT; t++) {
        int s = t & 1;
        if (t + 1 < NT) { stage(t + 1, s ^ 1); cp_wait<1>(); }
        else            { cp_wait<0>(); }
        __syncthreads();
        #pragma unroll 8
        for (int i = 0; i < P1_BN / 4; i++) {
            int row = i * 4 + l;
            float  a = tile[s][row][jl];
            float4 x = xs[s][row];
            a0 = __fmaf_rn(a, x.x, a0);
            a1 = __fmaf_rn(a, x.y, a1);
            a2 = __fmaf_rn(a, x.z, a2);
            a3 = __fmaf_rn(a, x.w, a3);
        }
        __syncthreads();
    }
    pacc[l][0][jl] = a0; pacc[l][1][jl] = a1;
    pacc[l][2][jl] = a2; pacc[l][3][jl] = a3;
    __syncthreads();
    // finalize: thread (f=l, jl): combine ((l0+l1)+(l2+l3))
    {
        int f = l;
        float x = __fadd_rn(__fadd_rn(pacc[0][f][jl], pacc[1][f][jl]),
                            __fadd_rn(pacc[2][f][jl], pacc[3][f][jl]));
        dst[(size_t)f * N_EDGES + j0 + jl] = x;
    }
}

// ---------------- phase 2: mi = (Ri.*e) @ bo, mo = (Ro.*e) @ bi (R8-proven) ----------------
// Ref semantics (confirmed): 4-lane mod-4 ascending FMA chains over j,
// term = fl32(A[n,j]*e[j]), combined ((l0+l1)+(l2+l3)).
// MAT-SERIALIZED: blocks [0,128) compute mi (reads Ri -> L2-warm from phase1),
// blocks [128,256) compute mo (Ro refills from DRAM meanwhile).
#define P2_NB  32
#define P2_JT  128
__global__ void __launch_bounds__(128) phase2_kernel(const float* __restrict__ Ri,
                                                     const float* __restrict__ Ro,
                                                     const float* __restrict__ e) {
    int mat = blockIdx.x >> 7;           // 0: mi (Ri, boT) first, 1: mo (Ro, biT)
    const float* A  = mat ? Ro : Ri;
    const float* BT = mat ? g_biT : g_boT;
    float* dst      = mat ? g_mo : g_mi;
    int n0  = (int)(blockIdx.x & 127) * P2_NB;
    int tid = threadIdx.x;
    int f = tid & 3, nl = tid >> 2;
    int n = n0 + nl;

    __shared__ __align__(16) float tile[2][P2_NB][P2_JT + 4];
    __shared__ float4 e4t[2][P2_JT / 4];
    __shared__ float4 btt[2][4][(P2_JT / 4) + 1];

    auto stage = [&](int t, int s) {
        int jt = t * P2_JT;
        const float* base = A + (size_t)n0 * N_EDGES + jt;
        #pragma unroll
        for (int o = 0; o < 8; o++) {
            int idx = o * 128 + tid;          // 1024 float4
            int row = idx >> 5, c4 = idx & 31;
            cp_async16(&tile[s][row][c4 * 4], base + (size_t)row * N_EDGES + c4 * 4);
        }
        if (tid < 32)
            cp_async16(&e4t[s][tid], e + jt + tid * 4);
        {
            int ff = tid >> 5, q = tid & 31;
            cp_async16(&btt[s][ff][q], BT + (size_t)ff * N_EDGES + jt + q * 4);
        }
        cp_commit();
    };

    stage(0, 0);
    float a0 = 0.f, a1 = 0.f, a2 = 0.f, a3 = 0.f;
    const int NT = N_EDGES / P2_JT;     // 64
    for (int t = 0; t < NT; t++) {
        int s = t & 1;
        if (t + 1 < NT) { stage(t + 1, s ^ 1); cp_wait<1>(); }
        else            { cp_wait<0>(); }
        __syncthreads();
        #pragma unroll
        for (int q = 0; q < P2_JT / 4; q++) {
            float4 av = *(const float4*)&tile[s][nl][q * 4];
            float4 ev = e4t[s][q];
            float4 bv = btt[s][f][q];
            a0 = __fmaf_rn(__fmul_rn(av.x, ev.x), bv.x, a0);
            a1 = __fmaf_rn(__fmul_rn(av.y, ev.y), bv.y, a1);
            a2 = __fmaf_rn(__fmul_rn(av.z, ev.z), bv.z, a2);
            a3 = __fmaf_rn(__fmul_rn(av.w, ev.w), bv.w, a3);
        }
        __syncthreads();
    }
    float x = __fadd_rn(__fadd_rn(a0, a1), __fadd_rn(a2, a3));
    dst[n * 4 + f] = x;
}

// ---------------- circuit: 8 register-resident passes (r8 version, proven) ----------------
#define SWZ(x) ((x) ^ (((x) >> 4) & 31))
#define PAT4(p, S0,S1,S2,S3) (((((p)>>0)&1)<<(S0)) | ((((p)>>1)&1)<<(S1)) | \
                              ((((p)>>2)&1)<<(S2)) | ((((p)>>3)&1)<<(S3)))
#define LD16(S0,S1,S2,S3) { _Pragma("unroll") \
    for (int p_ = 0; p_ < 16; p_++) v[p_] = st[sb ^ SWZ(PAT4(p_,S0,S1,S2,S3))]; }
#define ST16(S0,S1,S2,S3) { _Pragma("unroll") \
    for (int p_ = 0; p_ < 16; p_++) st[sb ^ SWZ(PAT4(p_,S0,S1,S2,S3))] = v[p_]; }
#define RY16(K, TI) { const float c_ = cst[TI], s_ = snt[TI]; \
    _Pragma("unroll") for (int i_ = 0; i_ < 16; i_++) if (!((i_ >> (K)) & 1)) { \
        int i1_ = i_ | (1 << (K)); \
        float a0_ = v[i_], a1_ = v[i1_]; \
        v[i_]  = c_ * a0_ - s_ * a1_; \
        v[i1_] = s_ * a0_ + c_ * a1_; } }
#define CX16(KC, KT) { _Pragma("unroll") \
    for (int i_ = 0; i_ < 16; i_++) if (((i_ >> (KC)) & 1) && !((i_ >> (KT)) & 1)) { \
        int i1_ = i_ | (1 << (KT)); \
        float tp_ = v[i_]; v[i_] = v[i1_]; v[i1_] = tp_; } }

__global__ void __launch_bounds__(256) circuit_kernel(const float* __restrict__ X,
                                                      float* __restrict__ out) {
    __shared__ float  st[DIMQ];
    __shared__ float  cw[12], sw[12];
    __shared__ float  cst[33], snt[33];
    __shared__ double redsm[8];

    int b = blockIdx.x, tid = threadIdx.x;

    if (tid < 12) {
        float angf = (tid < 4) ? g_mi[b * 4 + tid]
                   : (tid < 8) ? g_mo[b * 4 + tid - 4]
                               : X[b * 4 + tid - 8];
        double h = 0.5 * (double)angf;   // f64 trig: exact range reduction
        cw[tid] = (float)cos(h);
        sw[tid] = (float)sin(h);
    }
    if (tid < 33) { cst[tid] = g_cs[tid]; snt[tid] = g_sn[tid]; }
    __syncthreads();

    float v[16];

    // ---- PASS 1: S={7,8,9,10} (wires 4,3,2,1); init product fused in
    {
        int base = (tid & 127) | (((tid >> 7) & 1) << 11);
        float pb;
        pb  = ((base >> 11) & 1) ? sw[0]  : cw[0];
        pb *= ((base >> 6)  & 1) ? sw[5]  : cw[5];
        pb *= ((base >> 5)  & 1) ? sw[6]  : cw[6];
        pb *= ((base >> 4)  & 1) ? sw[7]  : cw[7];
        pb *= ((base >> 3)  & 1) ? sw[8]  : cw[8];
        pb *= ((base >> 2)  & 1) ? sw[9]  : cw[9];
        pb *= ((base >> 1)  & 1) ? sw[10] : cw[10];
        pb *= ((base >> 0)  & 1) ? sw[11] : cw[11];
        float f40 = cw[4], f41 = sw[4], f30 = cw[3], f31 = sw[3];
        float f20 = cw[2], f21 = sw[2], f10 = cw[1], f11 = sw[1];
        #pragma unroll
        for (int p = 0; p < 16; p++)
            v[p] = pb * ((p & 1) ? f41 : f40) * ((p & 2) ? f31 : f30)
                      * ((p & 4) ? f21 : f20) * ((p & 8) ? f11 : f10);
        RY16(3, 0)  RY16(2, 1)  CX16(3, 2)      // T0: cx1->2
        RY16(1, 2)  RY16(0, 3)  CX16(0, 1)      // T1: cx4->3
        int sb = SWZ(base);
        ST16(7, 8, 9, 10)
    }
    __syncthreads();

    // ---- PASS 2: S={3,4,5,6} (wires 8,7,6,5)
    {
        int base = (tid & 7) | (((tid >> 3) & 31) << 7);
        int sb = SWZ(base);
        LD16(3, 4, 5, 6)
        RY16(3, 4)  RY16(2, 5)  CX16(3, 2)      // T2: cx5->6
        RY16(1, 6)  RY16(0, 7)  CX16(1, 0)      // T3: cx7->8
        ST16(3, 4, 5, 6)
    }
    __syncthreads();

    // ---- PASS 3: S={1,2,10,11} (wires 10,9,1,0)
    {
        int base = (tid & 1) | (((tid >> 1) & 15) << 3) | (((tid >> 5) & 7) << 7);
        int sb = SWZ(base);
        LD16(1, 2, 10, 11)
        RY16(1, 8)  RY16(0, 9)  CX16(0, 1)      // T4: cx10->9
        RY16(3, 10) RY16(2, 11) CX16(3, 2)      // T5: cx0->1
        ST16(1, 2, 10, 11)
    }
    __syncthreads();

    // ---- PASS 4: S={6,7,8,9} (wires 5,4,3,2)
    {
        int base = (tid & 31) | (((tid >> 5) & 1) << 5) | (((tid >> 6) & 3) << 10);
        int sb = SWZ(base);
        LD16(6, 7, 8, 9)
        RY16(3, 12) RY16(2, 13) CX16(2, 3)      // T6: cx3->2
        RY16(1, 14) RY16(0, 15) CX16(1, 0)      // T7: cx4->5
        ST16(6, 7, 8, 9)
    }
    __syncthreads();

    // ---- PASS 5: S={2,3,4,5} (wires 9,8,7,6)
    {
        int base = (tid & 3) | (((tid >> 2) & 7) << 6) | (((tid >> 5) & 7) << 9);
        int sb = SWZ(base);
        LD16(2, 3, 4, 5)
        RY16(3, 16) RY16(2, 17) CX16(2, 3)      // T8: cx7->6
        RY16(1, 18) RY16(0, 19) CX16(1, 0)      // T9: cx8->9
        ST16(2, 3, 4, 5)
    }
    __syncthreads();

    // ---- PASS 6: S={0,1,6,9} (wires 11,10,5,2)
    {
        int base = ((tid & 15) << 2) | (((tid >> 4) & 1) << 8)
                 | (((tid >> 5) & 1) << 7) | (((tid >> 6) & 3) << 10);
        int sb = SWZ(base);
        LD16(0, 1, 6, 9)
        RY16(1, 20) RY16(0, 21) CX16(0, 1)      // T10: cx11->10
        RY16(3, 22) RY16(2, 23) CX16(2, 3)      // T11: cx5->2
        ST16(0, 1, 6, 9)
    }
    __syncthreads();

    // ---- PASS 7: S={2,5,9,10} (wires 9,6,2,1)
    {
        int base = (tid & 3) | (((tid >> 2) & 3) << 3) | (((tid >> 4) & 1) << 6)
                 | (((tid >> 5) & 3) << 7) | (((tid >> 7) & 1) << 11);
        int sb = SWZ(base);
        LD16(2, 5, 9, 10)
        RY16(1, 24) RY16(0, 25) CX16(1, 0)      // T12: cx6->9
        RY16(3, 26) RY16(2, 27) CX16(3, 2)      // T13: cx1->2
        ST16(2, 5, 9, 10)
    }
    __syncthreads();

    // ---- PASS 8: S={0,1,2,9} (wires 11,10,9,2); expz fused (slot 2 = wire 9)
    float local = 0.0f;
    {
        int base = ((tid & 15) << 3) | (((tid >> 4) & 1) << 8)
                 | (((tid >> 5) & 1) << 7) | (((tid >> 6) & 3) << 10);
        int sb = SWZ(base);
        LD16(0, 1, 2, 9)
        RY16(2, 28) RY16(1, 29) CX16(1, 2)      // T14: cx10->9
        RY16(3, 30) RY16(2, 31) CX16(3, 2)      // T15: cx2->9
        RY16(2, 32)                              // final ry@9
        #pragma unroll
        for (int p = 0; p < 16; p++) {
            float v2 = v[p] * v[p];
            local += (p & 4) ? -v2 : v2;
        }
    }

    double dv = (double)local;
    #pragma unroll
    for (int o = 16; o > 0; o >>= 1) dv += __shfl_down_sync(0xffffffffu, dv, o);
    int lane = tid & 31, wp = tid >> 5;
    if (lane == 0) redsm[wp] = dv;
    __syncthreads();
    if (tid == 0) {
        double expz = 0.0;
        for (int w = 0; w < 8; w++) expz += redsm[w];
        out[b] = (float)(1.5707963267948966 * (1.0 - expz));
    }
}

// ---------------- launch ----------------
extern "C" void kernel_launch(void* const* d_in, const int* in_sizes, int n_in,
                              void* d_out, int out_size) {
    const float *X = 0, *e = 0, *Ri = 0, *Ro = 0, *th = 0;
    for (int i = 0; i < n_in; i++) {
        int s = in_sizes[i];
        const float* p = (const float*)d_in[i];
        if (s == N_NODES * 4)            X = p;
        else if (s == N_EDGES)           e = p;
        else if (s == 33)                th = p;
        else if (s == N_NODES * N_EDGES) { if (!Ri) Ri = p; else Ro = p; }
    }
    float* out = (float*)d_out;

    phase1_kernel<<<(N_EDGES / P1_BJ) * 2, 128>>>(Ri, Ro, X, th);
    phase2_kernel<<<(N_NODES / P2_NB) * 2, 128>>>(Ri, Ro, e);
    circuit_kernel<<<N_NODES, 256>>>(X, out);
}

// round 16
// speedup vs baseline: 2.8812x; 1.0415x over previous
#include <cuda_runtime.h>
#include <math.h>

#define N_NODES 4096
#define N_EDGES 8192
#define DIMQ    4096

// ---------------- device scratch (no allocations allowed) ----------------
__device__ float g_boT[4 * N_EDGES];   // bo transposed [f][j], ref f32 semantics
__device__ float g_biT[4 * N_EDGES];
__device__ float g_mi[N_NODES * 4];
__device__ float g_mo[N_NODES * 4];
__device__ float g_cs[33];
__device__ float g_sn[33];

// ---------------- cp.async helpers ----------------
__device__ __forceinline__ unsigned smem_u32(const void* p) {
    return (unsigned)__cvta_generic_to_shared(p);
}
__device__ __forceinline__ void cp_async16(void* dst, const void* src) {
    asm volatile("cp.async.cg.shared.global [%0], [%1], 16;"
                 :: "r"(smem_u32(dst)), "l"(src));
}
__device__ __forceinline__ void cp_commit() {
    asm volatile("cp.async.commit_group;");
}
template<int N> __device__ __forceinline__ void cp_wait() {
    asm volatile("cp.async.wait_group %0;" :: "n"(N));
}

// ---------------- phase 1: bo = Ro^T X, bi = Ri^T X (R8-proven) ----------------
// Ref semantics (confirmed r6): per (j,f), 4 lanes over n==l (mod 4) ascending,
// acc_l = fma(A[n,j], X[n,f], acc_l); combine ((l0+l1)+(l2+l3)).
// MAT-SERIALIZED: blocks [0,256) process Ro, [256,512) Ri. Theta trig folded in.
#define P1_BJ 32
#define P1_BN 128
#define P1_LD 36
__global__ void __launch_bounds__(128) phase1_kernel(const float* __restrict__ Ri,
                                                     const float* __restrict__ Ro,
                                                     const float* __restrict__ X,
                                                     const float* __restrict__ theta) {
    int mat = blockIdx.x >> 8;                   // 0: Ro (first), 1: Ri (last)
    const float* A = mat ? Ri : Ro;
    float* dst     = mat ? g_biT : g_boT;
    int j0  = (int)(blockIdx.x & 255) * P1_BJ;
    int tid = threadIdx.x;
    int jl = tid & 31, l = tid >> 5;             // warp = lane index l

    if (blockIdx.x == 0 && tid < 33) {           // init fold (finishes in phase1)
        double h = 0.5 * (double)theta[tid];
        g_cs[tid] = (float)cos(h);
        g_sn[tid] = (float)sin(h);
    }

    __shared__ __align__(16) float  tile[2][P1_BN][P1_LD];
    __shared__ float4 xs[2][P1_BN];
    __shared__ float  pacc[4][4][32];            // [l][f][jl]

    auto stage = [&](int t, int s) {
        int n0 = t * P1_BN;
        const float* base = A + (size_t)n0 * N_EDGES + j0;
        #pragma unroll
        for (int o = 0; o < 8; o++) {
            int idx = o * 128 + tid;             // 1024 float4
            int row = idx >> 3, c4 = idx & 7;
            cp_async16(&tile[s][row][c4 * 4], base + (size_t)row * N_EDGES + c4 * 4);
        }
        cp_async16(&xs[s][tid], X + (size_t)(n0 + tid) * 4);
        cp_commit();
    };

    stage(0, 0);
    float a0 = 0.f, a1 = 0.f, a2 = 0.f, a3 = 0.f;
    const int NT = N_NODES / P1_BN;              // 32
    for (int t = 0; t < NT; t++) {
        int s = t & 1;
        if (t + 1 < NT) { stage(t + 1, s ^ 1); cp_wait<1>(); }
        else            { cp_wait<0>(); }
        __syncthreads();
        #pragma unroll 8
        for (int i = 0; i < P1_BN / 4; i++) {
            int row = i * 4 + l;
            float  a = tile[s][row][jl];
            float4 x = xs[s][row];
            a0 = __fmaf_rn(a, x.x, a0);
            a1 = __fmaf_rn(a, x.y, a1);
            a2 = __fmaf_rn(a, x.z, a2);
            a3 = __fmaf_rn(a, x.w, a3);
        }
        __syncthreads();
    }
    pacc[l][0][jl] = a0; pacc[l][1][jl] = a1;
    pacc[l][2][jl] = a2; pacc[l][3][jl] = a3;
    __syncthreads();
    // finalize: thread (f=l, jl): combine ((l0+l1)+(l2+l3))
    {
        int f = l;
        float x = __fadd_rn(__fadd_rn(pacc[0][f][jl], pacc[1][f][jl]),
                            __fadd_rn(pacc[2][f][jl], pacc[3][f][jl]));
        dst[(size_t)f * N_EDGES + j0 + jl] = x;
    }
}

// ---------------- phase 2: mi = (Ri.*e) @ bo, mo = (Ro.*e) @ bi ----------------
// Ref semantics (confirmed): 4-lane mod-4 ascending FMA chains over j,
// term = fl32(A[n,j]*e[j]), combined ((l0+l1)+(l2+l3)).
// 512 BLOCKS (P2_NB=16, 64 threads): doubles independent DRAM streams to match
// phase1's proven 512-block / 5.5 TB/s regime. Inner chain code unchanged.
#define P2_NB  16
#define P2_JT  128
__global__ void __launch_bounds__(64) phase2_kernel(const float* __restrict__ Ri,
                                                    const float* __restrict__ Ro,
                                                    const float* __restrict__ e) {
    int mat = blockIdx.x >> 8;           // 0: mi (Ri, boT) first, 1: mo (Ro, biT)
    const float* A  = mat ? Ro : Ri;
    const float* BT = mat ? g_biT : g_boT;
    float* dst      = mat ? g_mo : g_mi;
    int n0  = (int)(blockIdx.x & 255) * P2_NB;
    int tid = threadIdx.x;
    int f = tid & 3, nl = tid >> 2;      // nl 0..15
    int n = n0 + nl;

    __shared__ __align__(16) float tile[2][P2_NB][P2_JT + 4];
    __shared__ float4 e4t[2][P2_JT / 4];
    __shared__ float4 btt[2][4][(P2_JT / 4) + 1];

    auto stage = [&](int t, int s) {
        int jt = t * P2_JT;
        const float* base = A + (size_t)n0 * N_EDGES + jt;
        #pragma unroll
        for (int o = 0; o < 8; o++) {
            int idx = o * 64 + tid;           // 512 float4
            int row = idx >> 5, c4 = idx & 31;
            cp_async16(&tile[s][row][c4 * 4], base + (size_t)row * N_EDGES + c4 * 4);
        }
        if (tid < 32)
            cp_async16(&e4t[s][tid], e + jt + tid * 4);
        {
            int ff = tid >> 4, q = tid & 15;  // 64 threads cover 4 x 16, twice
            cp_async16(&btt[s][ff][q],      BT + (size_t)ff * N_EDGES + jt + q * 4);
            cp_async16(&btt[s][ff][q + 16], BT + (size_t)ff * N_EDGES + jt + (q + 16) * 4);
        }
        cp_commit();
    };

    stage(0, 0);
    float a0 = 0.f, a1 = 0.f, a2 = 0.f, a3 = 0.f;
    const int NT = N_EDGES / P2_JT;     // 64
    for (int t = 0; t < NT; t++) {
        int s = t & 1;
        if (t + 1 < NT) { stage(t + 1, s ^ 1); cp_wait<1>(); }
        else            { cp_wait<0>(); }
        __syncthreads();
        #pragma unroll
        for (int q = 0; q < P2_JT / 4; q++) {
            float4 av = *(const float4*)&tile[s][nl][q * 4];
            float4 ev = e4t[s][q];
            float4 bv = btt[s][f][q];
            a0 = __fmaf_rn(__fmul_rn(av.x, ev.x), bv.x, a0);
            a1 = __fmaf_rn(__fmul_rn(av.y, ev.y), bv.y, a1);
            a2 = __fmaf_rn(__fmul_rn(av.z, ev.z), bv.z, a2);
            a3 = __fmaf_rn(__fmul_rn(av.w, ev.w), bv.w, a3);
        }
        __syncthreads();
    }
    float x = __fadd_rn(__fadd_rn(a0, a1), __fadd_rn(a2, a3));
    dst[n * 4 + f] = x;
}

// ---------------- circuit: 8 register-resident passes (r8 version, proven) ----------------
#define SWZ(x) ((x) ^ (((x) >> 4) & 31))
#define PAT4(p, S0,S1,S2,S3) (((((p)>>0)&1)<<(S0)) | ((((p)>>1)&1)<<(S1)) | \
                              ((((p)>>2)&1)<<(S2)) | ((((p)>>3)&1)<<(S3)))
#define LD16(S0,S1,S2,S3) { _Pragma("unroll") \
    for (int p_ = 0; p_ < 16; p_++) v[p_] = st[sb ^ SWZ(PAT4(p_,S0,S1,S2,S3))]; }
#define ST16(S0,S1,S2,S3) { _Pragma("unroll") \
    for (int p_ = 0; p_ < 16; p_++) st[sb ^ SWZ(PAT4(p_,S0,S1,S2,S3))] = v[p_]; }
#define RY16(K, TI) { const float c_ = cst[TI], s_ = snt[TI]; \
    _Pragma("unroll") for (int i_ = 0; i_ < 16; i_++) if (!((i_ >> (K)) & 1)) { \
        int i1_ = i_ | (1 << (K)); \
        float a0_ = v[i_], a1_ = v[i1_]; \
        v[i_]  = c_ * a0_ - s_ * a1_; \
        v[i1_] = s_ * a0_ + c_ * a1_; } }
#define CX16(KC, KT) { _Pragma("unroll") \
    for (int i_ = 0; i_ < 16; i_++) if (((i_ >> (KC)) & 1) && !((i_ >> (KT)) & 1)) { \
        int i1_ = i_ | (1 << (KT)); \
        float tp_ = v[i_]; v[i_] = v[i1_]; v[i1_] = tp_; } }

__global__ void __launch_bounds__(256) circuit_kernel(const float* __restrict__ X,
                                                      float* __restrict__ out) {
    __shared__ float  st[DIMQ];
    __shared__ float  cw[12], sw[12];
    __shared__ float  cst[33], snt[33];
    __shared__ double redsm[8];

    int b = blockIdx.x, tid = threadIdx.x;

    if (tid < 12) {
        float angf = (tid < 4) ? g_mi[b * 4 + tid]
                   : (tid < 8) ? g_mo[b * 4 + tid - 4]
                               : X[b * 4 + tid - 8];
        double h = 0.5 * (double)angf;   // f64 trig: exact range reduction
        cw[tid] = (float)cos(h);
        sw[tid] = (float)sin(h);
    }
    if (tid < 33) { cst[tid] = g_cs[tid]; snt[tid] = g_sn[tid]; }
    __syncthreads();

    float v[16];

    // ---- PASS 1: S={7,8,9,10} (wires 4,3,2,1); init product fused in
    {
        int base = (tid & 127) | (((tid >> 7) & 1) << 11);
        float pb;
        pb  = ((base >> 11) & 1) ? sw[0]  : cw[0];
        pb *= ((base >> 6)  & 1) ? sw[5]  : cw[5];
        pb *= ((base >> 5)  & 1) ? sw[6]  : cw[6];
        pb *= ((base >> 4)  & 1) ? sw[7]  : cw[7];
        pb *= ((base >> 3)  & 1) ? sw[8]  : cw[8];
        pb *= ((base >> 2)  & 1) ? sw[9]  : cw[9];
        pb *= ((base >> 1)  & 1) ? sw[10] : cw[10];
        pb *= ((base >> 0)  & 1) ? sw[11] : cw[11];
        float f40 = cw[4], f41 = sw[4], f30 = cw[3], f31 = sw[3];
        float f20 = cw[2], f21 = sw[2], f10 = cw[1], f11 = sw[1];
        #pragma unroll
        for (int p = 0; p < 16; p++)
            v[p] = pb * ((p & 1) ? f41 : f40) * ((p & 2) ? f31 : f30)
                      * ((p & 4) ? f21 : f20) * ((p & 8) ? f11 : f10);
        RY16(3, 0)  RY16(2, 1)  CX16(3, 2)      // T0: cx1->2
        RY16(1, 2)  RY16(0, 3)  CX16(0, 1)      // T1: cx4->3
        int sb = SWZ(base);
        ST16(7, 8, 9, 10)
    }
    __syncthreads();

    // ---- PASS 2: S={3,4,5,6} (wires 8,7,6,5)
    {
        int base = (tid & 7) | (((tid >> 3) & 31) << 7);
        int sb = SWZ(base);
        LD16(3, 4, 5, 6)
        RY16(3, 4)  RY16(2, 5)  CX16(3, 2)      // T2: cx5->6
        RY16(1, 6)  RY16(0, 7)  CX16(1, 0)      // T3: cx7->8
        ST16(3, 4, 5, 6)
    }
    __syncthreads();

    // ---- PASS 3: S={1,2,10,11} (wires 10,9,1,0)
    {
        int base = (tid & 1) | (((tid >> 1) & 15) << 3) | (((tid >> 5) & 7) << 7);
        int sb = SWZ(base);
        LD16(1, 2, 10, 11)
        RY16(1, 8)  RY16(0, 9)  CX16(0, 1)      // T4: cx10->9
        RY16(3, 10) RY16(2, 11) CX16(3, 2)      // T5: cx0->1
        ST16(1, 2, 10, 11)
    }
    __syncthreads();

    // ---- PASS 4: S={6,7,8,9} (wires 5,4,3,2)
    {
        int base = (tid & 31) | (((tid >> 5) & 1) << 5) | (((tid >> 6) & 3) << 10);
        int sb = SWZ(base);
        LD16(6, 7, 8, 9)
        RY16(3, 12) RY16(2, 13) CX16(2, 3)      // T6: cx3->2
        RY16(1, 14) RY16(0, 15) CX16(1, 0)      // T7: cx4->5
        ST16(6, 7, 8, 9)
    }
    __syncthreads();

    // ---- PASS 5: S={2,3,4,5} (wires 9,8,7,6)
    {
        int base = (tid & 3) | (((tid >> 2) & 7) << 6) | (((tid >> 5) & 7) << 9);
        int sb = SWZ(base);
        LD16(2, 3, 4, 5)
        RY16(3, 16) RY16(2, 17) CX16(2, 3)      // T8: cx7->6
        RY16(1, 18) RY16(0, 19) CX16(1, 0)      // T9: cx8->9
        ST16(2, 3, 4, 5)
    }
    __syncthreads();

    // ---- PASS 6: S={0,1,6,9} (wires 11,10,5,2)
    {
        int base = ((tid & 15) << 2) | (((tid >> 4) & 1) << 8)
                 | (((tid >> 5) & 1) << 7) | (((tid >> 6) & 3) << 10);
        int sb = SWZ(base);
        LD16(0, 1, 6, 9)
        RY16(1, 20) RY16(0, 21) CX16(0, 1)      // T10: cx11->10
        RY16(3, 22) RY16(2, 23) CX16(2, 3)      // T11: cx5->2
        ST16(0, 1, 6, 9)
    }
    __syncthreads();

    // ---- PASS 7: S={2,5,9,10} (wires 9,6,2,1)
    {
        int base = (tid & 3) | (((tid >> 2) & 3) << 3) | (((tid >> 4) & 1) << 6)
                 | (((tid >> 5) & 3) << 7) | (((tid >> 7) & 1) << 11);
        int sb = SWZ(base);
        LD16(2, 5, 9, 10)
        RY16(1, 24) RY16(0, 25) CX16(1, 0)      // T12: cx6->9
        RY16(3, 26) RY16(2, 27) CX16(3, 2)      // T13: cx1->2
        ST16(2, 5, 9, 10)
    }
    __syncthreads();

    // ---- PASS 8: S={0,1,2,9} (wires 11,10,9,2); expz fused (slot 2 = wire 9)
    float local = 0.0f;
    {
        int base = ((tid & 15) << 3) | (((tid >> 4) & 1) << 8)
                 | (((tid >> 5) & 1) << 7) | (((tid >> 6) & 3) << 10);
        int sb = SWZ(base);
        LD16(0, 1, 2, 9)
        RY16(2, 28) RY16(1, 29) CX16(1, 2)      // T14: cx10->9
        RY16(3, 30) RY16(2, 31) CX16(3, 2)      // T15: cx2->9
        RY16(2, 32)                              // final ry@9
        #pragma unroll
        for (int p = 0; p < 16; p++) {
            float v2 = v[p] * v[p];
            local += (p & 4) ? -v2 : v2;
        }
    }

    double dv = (double)local;
    #pragma unroll
    for (int o = 16; o > 0; o >>= 1) dv += __shfl_down_sync(0xffffffffu, dv, o);
    int lane = tid & 31, wp = tid >> 5;
    if (lane == 0) redsm[wp] = dv;
    __syncthreads();
    if (tid == 0) {
        double expz = 0.0;
        for (int w = 0; w < 8; w++) expz += redsm[w];
        out[b] = (float)(1.5707963267948966 * (1.0 - expz));
    }
}

// ---------------- launch ----------------
extern "C" void kernel_launch(void* const* d_in, const int* in_sizes, int n_in,
                              void* d_out, int out_size) {
    const float *X = 0, *e = 0, *Ri = 0, *Ro = 0, *th = 0;
    for (int i = 0; i < n_in; i++) {
        int s = in_sizes[i];
        const float* p = (const float*)d_in[i];
        if (s == N_NODES * 4)            X = p;
        else if (s == N_EDGES)           e = p;
        else if (s == 33)                th = p;
        else if (s == N_NODES * N_EDGES) { if (!Ri) Ri = p; else Ro = p; }
    }
    float* out = (float*)d_out;

    phase1_kernel<<<(N_EDGES / P1_BJ) * 2, 128>>>(Ri, Ro, X, th);
    phase2_kernel<<<(N_NODES / P2_NB) * 2, 64>>>(Ri, Ro, e);
    circuit_kernel<<<N_NODES, 256>>>(X, out);
}